// round 1
// baseline (speedup 1.0000x reference)
#include <cuda_runtime.h>
#include <cstdint>

#define Bn 32
#define Cc 256
#define Gg 4
#define CG 64
#define Hh 56
#define Ww 56
#define OH 28
#define OW 28
#define Pp (OH*OW)          // 784
#define HWin (Hh*Ww)        // 3136
#define NOUT (Bn*Cc*Pp)     // 6422528
#define CNT (Bn*Pp)         // 25088 elements per channel
#define EPSBN 1e-5

// -------- scratch (device globals; no dynamic allocation) --------
__device__ unsigned long long g_packed1[Bn*Gg*HWin];   // sign(x) packed, 64 ch/word
__device__ unsigned long long g_packed2[Bn*Pp*4];      // sign(out1) packed, 256 ch -> 4 words
__device__ unsigned long long g_pw1[Cc*9];             // packed w1 signs [oc][tap]
__device__ unsigned long long g_pw2[Cc*4];             // packed w2 signs [oc][word]
__device__ float g_pool[NOUT];
__device__ short g_y1[NOUT];                           // conv1 raw int sums
__device__ short g_y2[NOUT];                           // conv2 raw int sums
__device__ float g_out1[NOUT];                         // x1 = bn1 + pool
__device__ float g_a1[Cc], g_b1[Cc], g_a2[Cc], g_b2[Cc];

// -------- pack weights (tiny) --------
__global__ void pack_w_kernel(const float* __restrict__ w1, const float* __restrict__ w2) {
    int tid = blockIdx.x * blockDim.x + threadIdx.x;
    if (tid < Cc * 9) {
        int oc = tid / 9, t = tid % 9;
        unsigned long long word = 0ull;
        #pragma unroll 8
        for (int ic = 0; ic < CG; ic++)
            if (w1[(oc * CG + ic) * 9 + t] > 0.f) word |= 1ull << ic;
        g_pw1[tid] = word;
    } else if (tid < Cc * 9 + Cc) {
        int oc = tid - Cc * 9;
        #pragma unroll
        for (int j = 0; j < 4; j++) {
            unsigned long long word = 0ull;
            #pragma unroll 8
            for (int i = 0; i < 64; i++)
                if (w2[oc * Cc + j * 64 + i] > 0.f) word |= 1ull << i;
            g_pw2[oc * 4 + j] = word;
        }
    }
}

// -------- pack sign(x): layout [n][g][ih*W+iw], bit = channel within group --------
__global__ void pack_x_kernel(const float* __restrict__ x) {
    int idx = blockIdx.x * blockDim.x + threadIdx.x;
    if (idx >= Bn * Gg * HWin) return;
    int pix = idx % HWin;
    int g   = (idx / HWin) % Gg;
    int n   = idx / (HWin * Gg);
    const float* xp = x + (size_t)(n * Cc + g * CG) * HWin + pix;
    unsigned long long word = 0ull;
    #pragma unroll 8
    for (int c = 0; c < CG; c++)
        if (xp[(size_t)c * HWin] > 0.f) word |= 1ull << c;
    g_packed1[idx] = word;
}

// -------- maxpool 3x3 s2 p1 (pad is -inf, so skipping OOB taps is exact) --------
__global__ void maxpool_kernel(const float* __restrict__ x) {
    int idx = blockIdx.x * blockDim.x + threadIdx.x;
    if (idx >= NOUT) return;
    int p = idx % Pp;
    int c = (idx / Pp) % Cc;
    int n = idx / (Pp * Cc);
    int oh = p / OW, ow = p % OW;
    const float* xp = x + (size_t)(n * Cc + c) * HWin;
    float m = -3.4e38f;
    #pragma unroll
    for (int kh = 0; kh < 3; kh++) {
        int ih = 2 * oh - 1 + kh;
        if (ih < 0 || ih >= Hh) continue;
        #pragma unroll
        for (int kw = 0; kw < 3; kw++) {
            int iw = 2 * ow - 1 + kw;
            if (iw < 0 || iw >= Ww) continue;
            m = fmaxf(m, xp[ih * Ww + iw]);
        }
    }
    g_pool[idx] = m;
}

// -------- conv1: grouped 3x3 s2 p1, XNOR-popcount. thread=(pixel, group) --------
__global__ void conv1_kernel() {
    __shared__ unsigned long long s_w[Cc * 9];
    int tflat = threadIdx.y * blockDim.x + threadIdx.x;
    for (int i = tflat; i < Cc * 9; i += 512) s_w[i] = g_pw1[i];
    __syncthreads();

    int n = blockIdx.x / 7;
    int p = (blockIdx.x % 7) * 128 + threadIdx.x;
    if (p >= Pp) return;
    int g = threadIdx.y;
    int oh = p / OW, ow = p % OW;

    unsigned long long xw[9], msk[9];
    int nv = 0;
    #pragma unroll
    for (int t = 0; t < 9; t++) {
        int kh = t / 3, kw = t % 3;
        int ih = 2 * oh - 1 + kh, iw = 2 * ow - 1 + kw;
        bool v = (ih >= 0) && (ih < Hh) && (iw >= 0) && (iw < Ww);
        xw[t]  = v ? g_packed1[(size_t)(n * Gg + g) * HWin + ih * Ww + iw] : 0ull;
        msk[t] = v ? ~0ull : 0ull;
        nv += v ? 1 : 0;
    }

    const unsigned long long* wp = s_w + g * CG * 9;
    short* yp = g_y1 + (size_t)(n * Cc + g * CG) * Pp + p;
    int base = 64 * nv;
    for (int oc = 0; oc < CG; oc++) {
        int m = 0;
        #pragma unroll
        for (int t = 0; t < 9; t++)
            m += __popcll((xw[t] ^ wp[oc * 9 + t]) & msk[t]);   // (a^b)&c -> one LOP3 per 32b
        yp[(size_t)oc * Pp] = (short)(base - 2 * m);
    }
}

// -------- training-mode BN stats over (N,H,W): exact integer sums --------
__global__ void bn_stats_kernel(int which, const float* __restrict__ gamma,
                                const float* __restrict__ beta) {
    const short* y = which ? g_y2 : g_y1;
    float* a = which ? g_a2 : g_a1;
    float* b = which ? g_b2 : g_b1;
    int c = blockIdx.x;
    int tid = threadIdx.x;

    long long s = 0, sq = 0;
    for (int i = tid; i < CNT; i += 256) {
        int n = i / Pp, p = i % Pp;
        int v = y[(size_t)(n * Cc + c) * Pp + p];
        s += v;
        sq += (long long)v * v;
    }
    __shared__ long long ss[256], ssq[256];
    ss[tid] = s; ssq[tid] = sq;
    __syncthreads();
    for (int o = 128; o > 0; o >>= 1) {
        if (tid < o) { ss[tid] += ss[tid + o]; ssq[tid] += ssq[tid + o]; }
        __syncthreads();
    }
    if (tid == 0) {
        double mu  = (double)ss[0] / (double)CNT;
        double var = (double)ssq[0] / (double)CNT - mu * mu;
        double ai  = (double)gamma[c] / sqrt(var + EPSBN);
        a[c] = (float)ai;
        b[c] = (float)((double)beta[c] - mu * ai);
    }
}

// -------- out1 = bn1(y1)+pool; also repack sign(out1): thread=(pixel, word_j) --------
__global__ void bn1_fuse_kernel() {
    int n = blockIdx.x / 7;
    int p = (blockIdx.x % 7) * 128 + threadIdx.x;
    if (p >= Pp) return;
    int j = threadIdx.y;  // which 64-channel word
    unsigned long long word = 0ull;
    #pragma unroll 4
    for (int c64 = 0; c64 < 64; c64++) {
        int c = j * 64 + c64;
        size_t idx = (size_t)(n * Cc + c) * Pp + p;
        float v = g_a1[c] * (float)g_y1[idx] + g_b1[c] + g_pool[idx];
        g_out1[idx] = v;
        if (v > 0.f) word |= 1ull << c64;
    }
    g_packed2[(size_t)(n * Pp + p) * 4 + j] = word;
}

// -------- conv2: 1x1, K=256 -> 4 popc words per output. thread=(pixel, c-quarter) --------
__global__ void conv2_kernel() {
    __shared__ unsigned long long s_w[Cc * 4];
    int tflat = threadIdx.y * blockDim.x + threadIdx.x;
    for (int i = tflat; i < Cc * 4; i += 512) s_w[i] = g_pw2[i];
    __syncthreads();

    int n = blockIdx.x / 7;
    int p = (blockIdx.x % 7) * 128 + threadIdx.x;
    if (p >= Pp) return;
    int q = threadIdx.y;

    size_t pb = (size_t)(n * Pp + p) * 4;
    unsigned long long xa0 = g_packed2[pb + 0];
    unsigned long long xa1 = g_packed2[pb + 1];
    unsigned long long xa2 = g_packed2[pb + 2];
    unsigned long long xa3 = g_packed2[pb + 3];

    short* yp = g_y2 + (size_t)(n * Cc + q * 64) * Pp + p;
    for (int c64 = 0; c64 < 64; c64++) {
        const unsigned long long* wp = s_w + (q * 64 + c64) * 4;
        int m = __popcll(xa0 ^ wp[0]) + __popcll(xa1 ^ wp[1])
              + __popcll(xa2 ^ wp[2]) + __popcll(xa3 ^ wp[3]);
        yp[(size_t)c64 * Pp] = (short)(256 - 2 * m);
    }
}

// -------- final: out = bn2(y2) + out1 --------
__global__ void final_kernel(float* __restrict__ out) {
    int idx = blockIdx.x * blockDim.x + threadIdx.x;
    if (idx >= NOUT) return;
    int c = (idx / Pp) % Cc;
    out[idx] = g_a2[c] * (float)g_y2[idx] + g_b2[c] + g_out1[idx];
}

extern "C" void kernel_launch(void* const* d_in, const int* in_sizes, int n_in,
                              void* d_out, int out_size) {
    const float* x      = (const float*)d_in[0];
    const float* w1     = (const float*)d_in[1];
    const float* w2     = (const float*)d_in[2];
    const float* gamma1 = (const float*)d_in[3];
    const float* beta1  = (const float*)d_in[4];
    const float* gamma2 = (const float*)d_in[5];
    const float* beta2  = (const float*)d_in[6];
    float* out = (float*)d_out;

    pack_w_kernel<<<10, 256>>>(w1, w2);
    pack_x_kernel<<<(Bn * Gg * HWin + 255) / 256, 256>>>(x);
    maxpool_kernel<<<(NOUT + 255) / 256, 256>>>(x);
    conv1_kernel<<<Bn * 7, dim3(128, 4)>>>();
    bn_stats_kernel<<<Cc, 256>>>(0, gamma1, beta1);
    bn1_fuse_kernel<<<Bn * 7, dim3(128, 4)>>>();
    conv2_kernel<<<Bn * 7, dim3(128, 4)>>>();
    bn_stats_kernel<<<Cc, 256>>>(1, gamma2, beta2);
    final_kernel<<<(NOUT + 255) / 256, 256>>>(out);
}

// round 2
// speedup vs baseline: 1.1802x; 1.1802x over previous
#include <cuda_runtime.h>
#include <cstdint>

#define Bn 32
#define Cc 256
#define Gg 4
#define CG 64
#define Hh 56
#define Ww 56
#define OH 28
#define OW 28
#define Pp (OH*OW)          // 784
#define HWin (Hh*Ww)        // 3136
#define NOUT (Bn*Cc*Pp)     // 6422528
#define CNT (Bn*Pp)         // 25088 elements per channel
#define NITEM (Bn*Pp)       // 25088 pixel items
#define EPSBN 1e-5

// -------- scratch (device globals; no dynamic allocation) --------
__device__ unsigned long long g_packed1[Bn*Gg*HWin];   // sign(x) packed, 64 ch/word
__device__ unsigned long long g_packed2[Bn*Pp*4];      // sign(out1) packed, 256 ch -> 4 words
__device__ unsigned long long g_pw1[Cc*9];             // packed w1 signs [oc][tap]
__device__ unsigned long long g_pw2[Cc*4];             // packed w2 signs [oc][word]
__device__ float g_pool[NOUT];
__device__ short g_y1[NOUT];                           // conv1 raw int sums
__device__ short g_y2[NOUT];                           // conv2 raw int sums
__device__ float g_out1[NOUT];                         // x1 = bn1 + pool
__device__ float g_a1[Cc], g_b1[Cc], g_a2[Cc], g_b2[Cc];

// -------- pack weights (tiny) --------
__global__ void pack_w_kernel(const float* __restrict__ w1, const float* __restrict__ w2) {
    int tid = blockIdx.x * blockDim.x + threadIdx.x;
    if (tid < Cc * 9) {
        int oc = tid / 9, t = tid % 9;
        unsigned long long word = 0ull;
        #pragma unroll 8
        for (int ic = 0; ic < CG; ic++)
            if (w1[(oc * CG + ic) * 9 + t] > 0.f) word |= 1ull << ic;
        g_pw1[tid] = word;
    } else if (tid < Cc * 9 + Cc) {
        int oc = tid - Cc * 9;
        #pragma unroll
        for (int j = 0; j < 4; j++) {
            unsigned long long word = 0ull;
            #pragma unroll 8
            for (int i = 0; i < 64; i++)
                if (w2[oc * Cc + j * 64 + i] > 0.f) word |= 1ull << i;
            g_pw2[oc * 4 + j] = word;
        }
    }
}

// -------- pack sign(x): layout [n][g][ih*W+iw], bit = channel within group --------
__global__ void pack_x_kernel(const float* __restrict__ x) {
    int idx = blockIdx.x * blockDim.x + threadIdx.x;
    if (idx >= Bn * Gg * HWin) return;
    int pix = idx % HWin;
    int g   = (idx / HWin) % Gg;
    int n   = idx / (HWin * Gg);
    const float* xp = x + (size_t)(n * Cc + g * CG) * HWin + pix;
    unsigned long long word = 0ull;
    #pragma unroll 8
    for (int c = 0; c < CG; c++)
        if (xp[(size_t)c * HWin] > 0.f) word |= 1ull << c;
    g_packed1[idx] = word;
}

// -------- maxpool 3x3 s2 p1 (pad is -inf, so skipping OOB taps is exact) --------
__global__ void maxpool_kernel(const float* __restrict__ x) {
    int idx = blockIdx.x * blockDim.x + threadIdx.x;
    if (idx >= NOUT) return;
    int p = idx % Pp;
    int c = (idx / Pp) % Cc;
    int n = idx / (Pp * Cc);
    int oh = p / OW, ow = p % OW;
    const float* xp = x + (size_t)(n * Cc + c) * HWin;
    float m = -3.4e38f;
    #pragma unroll
    for (int kh = 0; kh < 3; kh++) {
        int ih = 2 * oh - 1 + kh;
        if (ih < 0 || ih >= Hh) continue;
        #pragma unroll
        for (int kw = 0; kw < 3; kw++) {
            int iw = 2 * ow - 1 + kw;
            if (iw < 0 || iw >= Ww) continue;
            m = fmaxf(m, xp[ih * Ww + iw]);
        }
    }
    g_pool[idx] = m;
}

// -------- conv1: grouped 3x3 s2 p1, XNOR-popcount.
// grid (196, 4)=784 blocks; block (128,4). blockIdx.y = group.
// thread = one pixel item, 16 output channels (threadIdx.y picks the chunk).
__global__ void conv1_kernel() {
    __shared__ unsigned long long s_w[CG * 9];           // this group's weights only
    int g = blockIdx.y;
    int tflat = threadIdx.y * 128 + threadIdx.x;
    for (int i = tflat; i < CG * 9; i += 512) s_w[i] = g_pw1[g * CG * 9 + i];
    __syncthreads();

    int item = blockIdx.x * 128 + threadIdx.x;           // 0..25087 (=NITEM), exact
    int n = item / Pp, p = item % Pp;
    int oh = p / OW, ow = p % OW;

    unsigned long long xw[9], msk[9];
    int nv = 0;
    #pragma unroll
    for (int t = 0; t < 9; t++) {
        int kh = t / 3, kw = t % 3;
        int ih = 2 * oh - 1 + kh, iw = 2 * ow - 1 + kw;
        bool v = ((unsigned)ih < Hh) && ((unsigned)iw < Ww);
        xw[t]  = v ? g_packed1[(size_t)(n * Gg + g) * HWin + ih * Ww + iw] : 0ull;
        msk[t] = v ? ~0ull : 0ull;
        nv += v ? 1 : 0;
    }

    int base = 64 * nv;
    int oc0 = threadIdx.y * 16;
    short* yp = g_y1 + (size_t)(n * Cc + g * CG + oc0) * Pp + p;
    #pragma unroll
    for (int k = 0; k < 16; k++) {
        const unsigned long long* wp = s_w + (oc0 + k) * 9;
        int m = 0;
        #pragma unroll
        for (int t = 0; t < 9; t++)
            m += __popcll((xw[t] ^ wp[t]) & msk[t]);     // (a^b)&c -> one LOP3 per 32b
        yp[(size_t)k * Pp] = (short)(base - 2 * m);
    }
}

// -------- training-mode BN stats over (N,H,W): exact integer sums, short4 loads --------
__global__ void bn_stats_kernel(int which, const float* __restrict__ gamma,
                                const float* __restrict__ beta) {
    const short* y = which ? g_y2 : g_y1;
    float* a = which ? g_a2 : g_a1;
    float* b = which ? g_b2 : g_b1;
    int c = blockIdx.x;
    int tid = threadIdx.x;

    // per-thread partials fit int32 exactly: <=98 iters * 4 vals * 576^2 < 2^31
    int s = 0, sq = 0;
    for (int i = tid; i < CNT / 4; i += 256) {
        int n = i / (Pp / 4), p4 = i % (Pp / 4);
        short4 v = *(const short4*)(y + (size_t)(n * Cc + c) * Pp + p4 * 4);
        s  += v.x + v.y + v.z + v.w;
        sq += (int)v.x*v.x + (int)v.y*v.y + (int)v.z*v.z + (int)v.w*v.w;
    }
    __shared__ long long ss[256], ssq[256];
    ss[tid] = s; ssq[tid] = sq;
    __syncthreads();
    for (int o = 128; o > 0; o >>= 1) {
        if (tid < o) { ss[tid] += ss[tid + o]; ssq[tid] += ssq[tid + o]; }
        __syncthreads();
    }
    if (tid == 0) {
        double mu  = (double)ss[0] / (double)CNT;
        double var = (double)ssq[0] / (double)CNT - mu * mu;
        double ai  = (double)gamma[c] / sqrt(var + EPSBN);
        a[c] = (float)ai;
        b[c] = (float)((double)beta[c] - mu * ai);
    }
}

// -------- out1 = bn1(y1)+pool; also repack sign(out1): thread=(pixel, word_j) --------
__global__ void bn1_fuse_kernel() {
    int n = blockIdx.x / 7;
    int p = (blockIdx.x % 7) * 128 + threadIdx.x;
    if (p >= Pp) return;
    int j = threadIdx.y;  // which 64-channel word
    unsigned long long word = 0ull;
    #pragma unroll 4
    for (int c64 = 0; c64 < 64; c64++) {
        int c = j * 64 + c64;
        size_t idx = (size_t)(n * Cc + c) * Pp + p;
        float v = g_a1[c] * (float)g_y1[idx] + g_b1[c] + g_pool[idx];
        g_out1[idx] = v;
        if (v > 0.f) word |= 1ull << c64;
    }
    g_packed2[(size_t)(n * Pp + p) * 4 + j] = word;
}

// -------- conv2: 1x1, K=256. grid (196, 4); block (128,4).
// blockIdx.y = output-channel quarter; thread = pixel item, 16 oc.
__global__ void conv2_kernel() {
    __shared__ unsigned long long s_w[CG * 4];           // this quarter's weights
    int q = blockIdx.y;
    int tflat = threadIdx.y * 128 + threadIdx.x;
    for (int i = tflat; i < CG * 4; i += 512) s_w[i] = g_pw2[q * CG * 4 + i];
    __syncthreads();

    int item = blockIdx.x * 128 + threadIdx.x;           // = n*Pp + p
    size_t pb = (size_t)item * 4;
    unsigned long long xa0 = g_packed2[pb + 0];
    unsigned long long xa1 = g_packed2[pb + 1];
    unsigned long long xa2 = g_packed2[pb + 2];
    unsigned long long xa3 = g_packed2[pb + 3];

    int n = item / Pp, p = item % Pp;
    int oc0 = threadIdx.y * 16;
    short* yp = g_y2 + (size_t)(n * Cc + q * CG + oc0) * Pp + p;
    #pragma unroll
    for (int k = 0; k < 16; k++) {
        const unsigned long long* wp = s_w + (oc0 + k) * 4;
        int m = __popcll(xa0 ^ wp[0]) + __popcll(xa1 ^ wp[1])
              + __popcll(xa2 ^ wp[2]) + __popcll(xa3 ^ wp[3]);
        yp[(size_t)k * Pp] = (short)(256 - 2 * m);
    }
}

// -------- final: out = bn2(y2) + out1, vectorized x4 --------
__global__ void final_kernel(float* __restrict__ out) {
    int idx = blockIdx.x * blockDim.x + threadIdx.x;
    if (idx >= NOUT / 4) return;
    int e = idx * 4;
    int c = (e / Pp) % Cc;        // Pp % 4 == 0, so all 4 lanes share c
    short4 y  = *(const short4*)(g_y2 + e);
    float4 o1 = *(const float4*)(g_out1 + e);
    float a = g_a2[c], b = g_b2[c];
    float4 r;
    r.x = a * (float)y.x + b + o1.x;
    r.y = a * (float)y.y + b + o1.y;
    r.z = a * (float)y.z + b + o1.z;
    r.w = a * (float)y.w + b + o1.w;
    *(float4*)(out + e) = r;
}

extern "C" void kernel_launch(void* const* d_in, const int* in_sizes, int n_in,
                              void* d_out, int out_size) {
    const float* x      = (const float*)d_in[0];
    const float* w1     = (const float*)d_in[1];
    const float* w2     = (const float*)d_in[2];
    const float* gamma1 = (const float*)d_in[3];
    const float* beta1  = (const float*)d_in[4];
    const float* gamma2 = (const float*)d_in[5];
    const float* beta2  = (const float*)d_in[6];
    float* out = (float*)d_out;

    pack_w_kernel<<<10, 256>>>(w1, w2);
    pack_x_kernel<<<(Bn * Gg * HWin + 255) / 256, 256>>>(x);
    maxpool_kernel<<<(NOUT + 255) / 256, 256>>>(x);
    conv1_kernel<<<dim3(196, 4), dim3(128, 4)>>>();
    bn_stats_kernel<<<Cc, 256>>>(0, gamma1, beta1);
    bn1_fuse_kernel<<<Bn * 7, dim3(128, 4)>>>();
    conv2_kernel<<<dim3(196, 4), dim3(128, 4)>>>();
    bn_stats_kernel<<<Cc, 256>>>(1, gamma2, beta2);
    final_kernel<<<(NOUT / 4 + 255) / 256, 256>>>(out);
}

// round 3
// speedup vs baseline: 1.2828x; 1.0870x over previous
#include <cuda_runtime.h>
#include <cstdint>

#define Bn 32
#define Cc 256
#define Gg 4
#define CG 64
#define Hh 56
#define Ww 56
#define OH 28
#define OW 28
#define Pp (OH*OW)          // 784
#define HWin (Hh*Ww)        // 3136
#define NOUT (Bn*Cc*Pp)     // 6422528
#define CNT (Bn*Pp)         // 25088 elements per channel
#define NITEM (Bn*Pp)       // 25088 pixel items
#define EPSBN 1e-5

// -------- scratch (device globals; no dynamic allocation) --------
__device__ unsigned long long g_packed1[Bn*Gg*HWin];   // sign(x) packed, 64 ch/word
__device__ unsigned long long g_packed2[Bn*Pp*4];      // sign(out1) packed, 256 ch -> 4 words
__device__ unsigned long long g_pw1[Cc*9];             // packed w1 signs [oc][tap]
__device__ unsigned long long g_pw2[Cc*4];             // packed w2 signs [oc][word]
__device__ float g_pool[NOUT];
__device__ short g_y1[NOUT];                           // conv1 raw int sums
__device__ short g_y2[NOUT];                           // conv2 raw int sums
__device__ float g_a1[Cc], g_b1[Cc], g_a2[Cc], g_b2[Cc];

// -------- pack weights (tiny) --------
__global__ void pack_w_kernel(const float* __restrict__ w1, const float* __restrict__ w2) {
    int tid = blockIdx.x * blockDim.x + threadIdx.x;
    if (tid < Cc * 9) {
        int oc = tid / 9, t = tid % 9;
        unsigned long long word = 0ull;
        #pragma unroll 8
        for (int ic = 0; ic < CG; ic++)
            if (w1[(oc * CG + ic) * 9 + t] > 0.f) word |= 1ull << ic;
        g_pw1[tid] = word;
    } else if (tid < Cc * 9 + Cc) {
        int oc = tid - Cc * 9;
        #pragma unroll
        for (int j = 0; j < 4; j++) {
            unsigned long long word = 0ull;
            #pragma unroll 8
            for (int i = 0; i < 64; i++)
                if (w2[oc * Cc + j * 64 + i] > 0.f) word |= 1ull << i;
            g_pw2[oc * 4 + j] = word;
        }
    }
}

// -------- pack sign(x): layout [n][g][ih*W+iw], bit = channel within group --------
__global__ void pack_x_kernel(const float* __restrict__ x) {
    int idx = blockIdx.x * blockDim.x + threadIdx.x;
    if (idx >= Bn * Gg * HWin) return;
    int pix = idx % HWin;
    int g   = (idx / HWin) % Gg;
    int n   = idx / (HWin * Gg);
    const float* xp = x + (size_t)(n * Cc + g * CG) * HWin + pix;
    unsigned long long word = 0ull;
    #pragma unroll 8
    for (int c = 0; c < CG; c++)
        if (xp[(size_t)c * HWin] > 0.f) word |= 1ull << c;
    g_packed1[idx] = word;
}

// -------- maxpool 3x3 s2 p1 (pad is -inf, so skipping OOB taps is exact) --------
__global__ void maxpool_kernel(const float* __restrict__ x) {
    int idx = blockIdx.x * blockDim.x + threadIdx.x;
    if (idx >= NOUT) return;
    int p = idx % Pp;
    int c = (idx / Pp) % Cc;
    int n = idx / (Pp * Cc);
    int oh = p / OW, ow = p % OW;
    const float* xp = x + (size_t)(n * Cc + c) * HWin;
    float m = -3.4e38f;
    #pragma unroll
    for (int kh = 0; kh < 3; kh++) {
        int ih = 2 * oh - 1 + kh;
        if (ih < 0 || ih >= Hh) continue;
        #pragma unroll
        for (int kw = 0; kw < 3; kw++) {
            int iw = 2 * ow - 1 + kw;
            if (iw < 0 || iw >= Ww) continue;
            m = fmaxf(m, xp[ih * Ww + iw]);
        }
    }
    g_pool[idx] = m;
}

// -------- conv1: grouped 3x3 s2 p1, XNOR-popcount.
// grid (196, 8); block (128,4). blockIdx.y: bits[2:1]=group, bit0=oc half.
// thread = one pixel item, 8 output channels.
__global__ void __launch_bounds__(512) conv1_kernel() {
    __shared__ unsigned long long s_w[32 * 9];           // this (group, half)'s weights
    int g    = blockIdx.y >> 1;
    int half = blockIdx.y & 1;
    int tflat = threadIdx.y * 128 + threadIdx.x;
    for (int i = tflat; i < 32 * 9; i += 512)
        s_w[i] = g_pw1[(g * CG + half * 32) * 9 + i];
    __syncthreads();

    int item = blockIdx.x * 128 + threadIdx.x;           // 0..25087 exact
    int n = item / Pp, p = item % Pp;
    int oh = p / OW, ow = p % OW;

    unsigned long long xw[9], msk[9];
    int nv = 0;
    #pragma unroll
    for (int t = 0; t < 9; t++) {
        int kh = t / 3, kw = t % 3;
        int ih = 2 * oh - 1 + kh, iw = 2 * ow - 1 + kw;
        bool v = ((unsigned)ih < Hh) && ((unsigned)iw < Ww);
        xw[t]  = v ? g_packed1[(size_t)(n * Gg + g) * HWin + ih * Ww + iw] : 0ull;
        msk[t] = v ? ~0ull : 0ull;
        nv += v ? 1 : 0;
    }

    int base = 64 * nv;
    int ocs = threadIdx.y * 8;                           // within this 32-oc half
    short* yp = g_y1 + (size_t)(n * Cc + g * CG + half * 32 + ocs) * Pp + p;
    #pragma unroll
    for (int k = 0; k < 8; k++) {
        const unsigned long long* wp = s_w + (ocs + k) * 9;
        int m = 0;
        #pragma unroll
        for (int t = 0; t < 9; t++)
            m += __popcll((xw[t] ^ wp[t]) & msk[t]);     // (a^b)&c -> one LOP3 per 32b
        yp[(size_t)k * Pp] = (short)(base - 2 * m);
    }
}

// -------- training-mode BN stats over (N,H,W): exact integer sums, short4 loads --------
__global__ void bn_stats_kernel(int which, const float* __restrict__ gamma,
                                const float* __restrict__ beta) {
    const short* y = which ? g_y2 : g_y1;
    float* a = which ? g_a2 : g_a1;
    float* b = which ? g_b2 : g_b1;
    int c = blockIdx.x;
    int tid = threadIdx.x;

    int s = 0, sq = 0;   // exact: <=98 iters * 4 vals * 576^2 < 2^31
    for (int i = tid; i < CNT / 4; i += 256) {
        int n = i / (Pp / 4), p4 = i % (Pp / 4);
        short4 v = *(const short4*)(y + (size_t)(n * Cc + c) * Pp + p4 * 4);
        s  += v.x + v.y + v.z + v.w;
        sq += (int)v.x*v.x + (int)v.y*v.y + (int)v.z*v.z + (int)v.w*v.w;
    }
    __shared__ long long ss[256], ssq[256];
    ss[tid] = s; ssq[tid] = sq;
    __syncthreads();
    for (int o = 128; o > 0; o >>= 1) {
        if (tid < o) { ss[tid] += ss[tid + o]; ssq[tid] += ssq[tid + o]; }
        __syncthreads();
    }
    if (tid == 0) {
        double mu  = (double)ss[0] / (double)CNT;
        double var = (double)ssq[0] / (double)CNT - mu * mu;
        double ai  = (double)gamma[c] / sqrt(var + EPSBN);
        a[c] = (float)ai;
        b[c] = (float)((double)beta[c] - mu * ai);
    }
}

// -------- binarize out1 = bn1(y1)+pool into packed words (no out1 store) --------
__global__ void bn1_fuse_kernel() {
    int n = blockIdx.x / 7;
    int p = (blockIdx.x % 7) * 128 + threadIdx.x;
    if (p >= Pp) return;
    int j = threadIdx.y;  // which 64-channel word
    unsigned long long word = 0ull;
    #pragma unroll 4
    for (int c64 = 0; c64 < 64; c64++) {
        int c = j * 64 + c64;
        size_t idx = (size_t)(n * Cc + c) * Pp + p;
        float v = g_a1[c] * (float)g_y1[idx] + g_b1[c] + g_pool[idx];
        if (v > 0.f) word |= 1ull << c64;
    }
    g_packed2[(size_t)(n * Pp + p) * 4 + j] = word;
}

// -------- conv2: 1x1, K=256. grid (196, 8); block (128,4).
// blockIdx.y = 32-oc chunk; thread = pixel item, 8 oc.
__global__ void __launch_bounds__(512) conv2_kernel() {
    __shared__ unsigned long long s_w[32 * 4];
    int q = blockIdx.y;                                  // 32-oc chunk index
    int tflat = threadIdx.y * 128 + threadIdx.x;
    for (int i = tflat; i < 32 * 4; i += 512) s_w[i] = g_pw2[q * 32 * 4 + i];
    __syncthreads();

    int item = blockIdx.x * 128 + threadIdx.x;           // = n*Pp + p
    size_t pb = (size_t)item * 4;
    unsigned long long xa0 = g_packed2[pb + 0];
    unsigned long long xa1 = g_packed2[pb + 1];
    unsigned long long xa2 = g_packed2[pb + 2];
    unsigned long long xa3 = g_packed2[pb + 3];

    int n = item / Pp, p = item % Pp;
    int ocs = threadIdx.y * 8;
    short* yp = g_y2 + (size_t)(n * Cc + q * 32 + ocs) * Pp + p;
    #pragma unroll
    for (int k = 0; k < 8; k++) {
        const unsigned long long* wp = s_w + (ocs + k) * 4;
        int m = __popcll(xa0 ^ wp[0]) + __popcll(xa1 ^ wp[1])
              + __popcll(xa2 ^ wp[2]) + __popcll(xa3 ^ wp[3]);
        yp[(size_t)k * Pp] = (short)(256 - 2 * m);
    }
}

// -------- final: out = bn2(y2) + bn1(y1) + pool, vectorized x4 --------
__global__ void final_kernel(float* __restrict__ out) {
    int idx = blockIdx.x * blockDim.x + threadIdx.x;
    if (idx >= NOUT / 4) return;
    int e = idx * 4;
    int c = (e / Pp) % Cc;        // Pp % 4 == 0, so all 4 lanes share c
    short4 y2 = *(const short4*)(g_y2 + e);
    short4 y1 = *(const short4*)(g_y1 + e);
    float4 pl = *(const float4*)(g_pool + e);
    float a2 = g_a2[c], b2 = g_b2[c];
    float a1 = g_a1[c], b1 = g_b1[c];
    float bb = b1 + b2;
    float4 r;
    r.x = a2 * (float)y2.x + a1 * (float)y1.x + bb + pl.x;
    r.y = a2 * (float)y2.y + a1 * (float)y1.y + bb + pl.y;
    r.z = a2 * (float)y2.z + a1 * (float)y1.z + bb + pl.z;
    r.w = a2 * (float)y2.w + a1 * (float)y1.w + bb + pl.w;
    *(float4*)(out + e) = r;
}

extern "C" void kernel_launch(void* const* d_in, const int* in_sizes, int n_in,
                              void* d_out, int out_size) {
    const float* x      = (const float*)d_in[0];
    const float* w1     = (const float*)d_in[1];
    const float* w2     = (const float*)d_in[2];
    const float* gamma1 = (const float*)d_in[3];
    const float* beta1  = (const float*)d_in[4];
    const float* gamma2 = (const float*)d_in[5];
    const float* beta2  = (const float*)d_in[6];
    float* out = (float*)d_out;

    pack_w_kernel<<<10, 256>>>(w1, w2);
    pack_x_kernel<<<(Bn * Gg * HWin + 255) / 256, 256>>>(x);
    maxpool_kernel<<<(NOUT + 255) / 256, 256>>>(x);
    conv1_kernel<<<dim3(196, 8), dim3(128, 4)>>>();
    bn_stats_kernel<<<Cc, 256>>>(0, gamma1, beta1);
    bn1_fuse_kernel<<<Bn * 7, dim3(128, 4)>>>();
    conv2_kernel<<<dim3(196, 8), dim3(128, 4)>>>();
    bn_stats_kernel<<<Cc, 256>>>(1, gamma2, beta2);
    final_kernel<<<(NOUT / 4 + 255) / 256, 256>>>(out);
}